// round 3
// baseline (speedup 1.0000x reference)
#include <cuda_runtime.h>
#include <math.h>
#include <stdint.h>

// Problem constants
#define BB 256
#define TT 128
#define EE 300
#define HH 2048
#define GG 8192   // 4*H

// Scratch (device globals -- no allocation allowed)
__device__ float g_xg[(size_t)BB * TT * GG];   // [B*T, 4H] precomputed input gates (1 GiB)
__device__ float g_gates[(size_t)BB * GG];     // per-step gate pre-activations
__device__ float g_h[(size_t)BB * HH];
__device__ float g_c[(size_t)BB * HH];

// ---------------------------------------------------------------------------
// Zero h, c each launch (graph replays must be deterministic)
// ---------------------------------------------------------------------------
__global__ void init_state_kernel() {
    int i = blockIdx.x * blockDim.x + threadIdx.x;
    if (i < BB * HH) { g_h[i] = 0.0f; g_c[i] = 0.0f; }
}

// ---------------------------------------------------------------------------
// Generic NT GEMM: C[m, n] = sum_k A[m,k] * Bm[n,k]  (+ bias[n]) (+ addend[m,n])
//   A row stride == K, Bm row stride == K, C row stride == GG (8192)
//   BM=BN=128, BK=8, 256 threads, 8x8 per thread.
//   Requires: M,N multiples of 128; K multiple of 4.
// ---------------------------------------------------------------------------
__global__ void __launch_bounds__(256) gemm_nt_128(
    const float* __restrict__ A,
    const float* __restrict__ Bm,
    float* __restrict__ C,
    int K,
    const float* __restrict__ bias0,   // per-column, nullable
    const float* __restrict__ bias1,   // per-column, nullable
    const float* __restrict__ addend,  // [M rows, stride addStride], nullable
    int addStride)
{
    __shared__ float As[8][128];
    __shared__ float Bs[8][128];

    const int tid = threadIdx.x;
    const int tx = tid & 15;        // 0..15 -> N direction
    const int ty = tid >> 4;        // 0..15 -> M direction
    const int tileN = blockIdx.x * 128;
    const int tileM = blockIdx.y * 128;

    const int lrow = tid >> 1;          // 0..127 row loaded by this thread
    const int lkb  = (tid & 1) * 4;     // 0 or 4, k sub-offset

    const float* Aptr = A + (size_t)(tileM + lrow) * K;
    const float* Bptr = Bm + (size_t)(tileN + lrow) * K;

    float acc[8][8];
#pragma unroll
    for (int i = 0; i < 8; i++)
#pragma unroll
        for (int j = 0; j < 8; j++) acc[i][j] = 0.0f;

    for (int k0 = 0; k0 < K; k0 += 8) {
        const int k = k0 + lkb;
        float4 av, bv;
        if (k < K) {   // K % 4 == 0 guarantees full float4 if k < K
            av = *(const float4*)(Aptr + k);
            bv = *(const float4*)(Bptr + k);
        } else {
            av = make_float4(0.f, 0.f, 0.f, 0.f);
            bv = make_float4(0.f, 0.f, 0.f, 0.f);
        }
        As[lkb + 0][lrow] = av.x;
        As[lkb + 1][lrow] = av.y;
        As[lkb + 2][lrow] = av.z;
        As[lkb + 3][lrow] = av.w;
        Bs[lkb + 0][lrow] = bv.x;
        Bs[lkb + 1][lrow] = bv.y;
        Bs[lkb + 2][lrow] = bv.z;
        Bs[lkb + 3][lrow] = bv.w;
        __syncthreads();

#pragma unroll
        for (int kk = 0; kk < 8; kk++) {
            float a[8], b[8];
            float4 a0 = *(const float4*)&As[kk][ty * 8];
            float4 a1 = *(const float4*)&As[kk][ty * 8 + 4];
            float4 b0 = *(const float4*)&Bs[kk][tx * 8];
            float4 b1 = *(const float4*)&Bs[kk][tx * 8 + 4];
            a[0]=a0.x; a[1]=a0.y; a[2]=a0.z; a[3]=a0.w;
            a[4]=a1.x; a[5]=a1.y; a[6]=a1.z; a[7]=a1.w;
            b[0]=b0.x; b[1]=b0.y; b[2]=b0.z; b[3]=b0.w;
            b[4]=b1.x; b[5]=b1.y; b[6]=b1.z; b[7]=b1.w;
#pragma unroll
            for (int i = 0; i < 8; i++)
#pragma unroll
                for (int j = 0; j < 8; j++)
                    acc[i][j] = fmaf(a[i], b[j], acc[i][j]);
        }
        __syncthreads();
    }

    // Epilogue
#pragma unroll
    for (int i = 0; i < 8; i++) {
        const int row = tileM + ty * 8 + i;
        const float* addRow = addend ? (addend + (size_t)row * addStride) : nullptr;
        float* Crow = C + (size_t)row * GG;
#pragma unroll
        for (int j = 0; j < 8; j++) {
            const int col = tileN + tx * 8 + j;
            float v = acc[i][j];
            if (bias0) v += bias0[col] + bias1[col];
            if (addRow) v += addRow[col];
            Crow[col] = v;
        }
    }
}

// ---------------------------------------------------------------------------
// Pointwise LSTM cell update: reads g_gates (pre-activations), updates g_h/g_c.
// out != nullptr on the final timestep -> also writes d_out.
// ---------------------------------------------------------------------------
__device__ __forceinline__ float sigmoidf_(float x) {
    return 1.0f / (1.0f + expf(-x));
}

__global__ void lstm_pointwise_kernel(float* __restrict__ out) {
    int idx = blockIdx.x * blockDim.x + threadIdx.x;
    if (idx >= BB * HH) return;
    const int b = idx >> 11;          // /H
    const int j = idx & (HH - 1);
    const float* gr = g_gates + (size_t)b * GG;
    const float vi = gr[j];
    const float vf = gr[HH + j];
    const float vg = gr[2 * HH + j];
    const float vo = gr[3 * HH + j];
    const float ig = sigmoidf_(vi);
    const float fg = sigmoidf_(vf);
    const float gg = tanhf(vg);
    const float og = sigmoidf_(vo);
    const float cn = fg * g_c[idx] + ig * gg;
    const float hn = og * tanhf(cn);
    g_c[idx] = cn;
    g_h[idx] = hn;
    if (out) out[idx] = hn;
}

// ---------------------------------------------------------------------------
// Launch
// ---------------------------------------------------------------------------
extern "C" void kernel_launch(void* const* d_in, const int* in_sizes, int n_in,
                              void* d_out, int out_size) {
    const float* x    = (const float*)d_in[0];   // [B, T, E]
    const float* W_ih = (const float*)d_in[1];   // [4H, E]
    const float* W_hh = (const float*)d_in[2];   // [4H, H]
    const float* b_ih = (const float*)d_in[3];   // [4H]
    const float* b_hh = (const float*)d_in[4];   // [4H]
    float* out = (float*)d_out;                  // [B, H]

    float *xg_p, *gates_p, *h_p;
    cudaGetSymbolAddress((void**)&xg_p, g_xg);
    cudaGetSymbolAddress((void**)&gates_p, g_gates);
    cudaGetSymbolAddress((void**)&h_p, g_h);

    // Reset recurrent state
    init_state_kernel<<<(BB * HH + 255) / 256, 256>>>();

    // Phase 1: xg[b*T+t, :] = x[b,t,:] @ W_ih^T + b_ih + b_hh
    {
        dim3 grid(GG / 128, (BB * TT) / 128);   // 64 x 256
        gemm_nt_128<<<grid, 256>>>(x, W_ih, xg_p, EE, b_ih, b_hh, nullptr, 0);
    }

    // Phase 2: recurrence
    for (int t = 0; t < TT; t++) {
        dim3 grid(GG / 128, BB / 128);          // 64 x 2
        // gates[b, :] = h[b,:] @ W_hh^T + xg[b*T + t, :]
        gemm_nt_128<<<grid, 256>>>(h_p, W_hh, gates_p, HH,
                                   nullptr, nullptr,
                                   xg_p + (size_t)t * GG, TT * GG);
        lstm_pointwise_kernel<<<(BB * HH + 255) / 256, 256>>>(
            (t == TT - 1) ? out : nullptr);
    }
}

// round 6
// speedup vs baseline: 4.0474x; 4.0474x over previous
#include <cuda_runtime.h>
#include <cuda_bf16.h>
#include <stdint.h>
#include <math.h>

// ---------------------------------------------------------------------------
// Problem constants
// ---------------------------------------------------------------------------
#define BB 256
#define TT 128
#define EE 300
#define HH 2048
#define GG 8192      // 4*H

#define KSEG_R 2048  // recurrence K segment (hi / lo halves)
#define KSEG_X 320   // phase-1 K segment (300 padded to 320)
#define LDA_R 4096   // 2*KSEG_R  (row stride of split h / split W_hh)
#define LDA_X 640    // 2*KSEG_X

#define TILE_BYTES 16384            // 128 rows x 128 bytes (64 bf16)
#define BUF_BYTES  (4*TILE_BYTES)   // AHI | ALO | BHI | BLO
#define SMEM_DYN   (2*BUF_BYTES)    // double buffered = 131072 B

// ---------------------------------------------------------------------------
// Device scratch (no allocations allowed)
// ---------------------------------------------------------------------------
__device__ float                      g_xg[(size_t)BB * TT * GG];   // [B*T][8192] gate-interleaved
__device__ __align__(16) __nv_bfloat16 g_whh[(size_t)GG * LDA_R];   // reordered rows: [Whi | Wlo]
__device__ __align__(16) __nv_bfloat16 g_wih[(size_t)GG * LDA_X];   // reordered rows: [Whi | Wlo], K padded
__device__ __align__(16) __nv_bfloat16 g_xs[(size_t)BB * TT * LDA_X]; // [x_hi | x_lo], K padded
__device__ __align__(16) __nv_bfloat16 g_hs[2][(size_t)BB * LDA_R]; // ping-pong split h: [h_hi | h_lo]
__device__ float                      g_c[(size_t)BB * HH];
__device__ float                      g_bias[GG];                    // reordered b_ih + b_hh

// ---------------------------------------------------------------------------
// PTX helpers (baseline ISA only: cp.async / ldmatrix / mma.sync -- sm_80+)
// ---------------------------------------------------------------------------
__device__ __forceinline__ uint32_t smem_u32(const void* p) {
    uint32_t a;
    asm("{ .reg .u64 t; cvta.to.shared.u64 t, %1; cvt.u32.u64 %0, t; }" : "=r"(a) : "l"(p));
    return a;
}

#define CP_ASYNC16(sa, ga) \
    asm volatile("cp.async.cg.shared.global [%0], [%1], 16;" :: "r"(sa), "l"(ga))
#define CP_COMMIT() asm volatile("cp.async.commit_group;")
#define CP_WAIT1()  asm volatile("cp.async.wait_group 1;")
#define CP_WAIT0()  asm volatile("cp.async.wait_group 0;")

#define LDSM_X4(r0, r1, r2, r3, addr) \
    asm volatile("ldmatrix.sync.aligned.m8n8.x4.shared.b16 {%0,%1,%2,%3}, [%4];" \
                 : "=r"(r0), "=r"(r1), "=r"(r2), "=r"(r3) : "r"(addr))

#define MMA_BF16(d, a, b) \
    asm volatile("mma.sync.aligned.m16n8k16.row.col.f32.bf16.bf16.f32 " \
                 "{%0,%1,%2,%3}, {%4,%5,%6,%7}, {%8,%9}, {%0,%1,%2,%3};" \
                 : "+f"((d)[0]), "+f"((d)[1]), "+f"((d)[2]), "+f"((d)[3]) \
                 : "r"((a)[0]), "r"((a)[1]), "r"((a)[2]), "r"((a)[3]), \
                   "r"((b)[0]), "r"((b)[1]))

// ---------------------------------------------------------------------------
// Unified split-bf16 HMMA GEMM.
//  C_tile[128m x 128n] = A[128, 2*kseg] x B[128, 2*kseg]^T with the 3-term
//  split accumulation: Ahi*Bhi + Alo*Bhi + Ahi*Blo (fp32 accumulate).
//  mode 0: write g_xg (+bias).   mode 1: fused LSTM cell epilogue at step t.
//  8 warps: 4 (M) x 2 (N); warp tile 32 x 64.
// ---------------------------------------------------------------------------
__global__ void __launch_bounds__(256, 1)
gemm_split_kernel(const __nv_bfloat16* __restrict__ A,
                  const __nv_bfloat16* __restrict__ Bw,
                  int lda, int kseg, int niter,
                  int mode, int t, float* __restrict__ out)
{
    extern __shared__ char smem[];
    const int tid  = threadIdx.x;
    const int lane = tid & 31;
    const int wid  = tid >> 5;
    const int wm   = wid >> 1;      // 0..3  (M direction)
    const int wn   = wid & 1;       // 0..1  (N direction)
    const int tileN = blockIdx.x;
    const int tileM = blockIdx.y;
    const uint32_t sbase = smem_u32(smem);

    const __nv_bfloat16* aBase = A  + (size_t)(tileM * 128) * lda;
    const __nv_bfloat16* bBase = Bw + (size_t)(tileN * 128) * lda;

    float acc[2][8][4];
#pragma unroll
    for (int m = 0; m < 2; m++)
#pragma unroll
        for (int n = 0; n < 8; n++)
#pragma unroll
            for (int v = 0; v < 4; v++) acc[m][n][v] = 0.0f;

    // ---- async tile loader: 4 tiles x 128 rows x 8 16B-blocks, XOR swizzle
    auto issue_loads = [&](int it) {
        const int buf = it & 1;
        const int k0  = it * 64;
        const uint32_t sb = sbase + buf * BUF_BYTES;
#pragma unroll
        for (int s = 0; s < 16; s++) {
            const int linear = tid + s * 256;     // 0..4095
            const int tile = linear >> 10;        // 0..3
            const int rem  = linear & 1023;
            const int r    = rem >> 3;            // 0..127
            const int kb   = rem & 7;             // 0..7 (16B blocks)
            const __nv_bfloat16* g;
            if (tile == 0)      g = aBase + (size_t)r * lda + k0 + kb * 8;
            else if (tile == 1) g = aBase + (size_t)r * lda + kseg + k0 + kb * 8;
            else if (tile == 2) g = bBase + (size_t)r * lda + k0 + kb * 8;
            else                g = bBase + (size_t)r * lda + kseg + k0 + kb * 8;
            const uint32_t sa = sb + tile * TILE_BYTES + r * 128 + ((kb ^ (r & 7)) << 4);
            CP_ASYNC16(sa, g);
        }
        CP_COMMIT();
    };

    // ---- compute one 64-wide K chunk from buffer buf
    auto compute = [&](int buf) {
        const uint32_t sb   = sbase + buf * BUF_BYTES;
        const uint32_t aHiB = sb;
        const uint32_t aLoB = sb + TILE_BYTES;
        const uint32_t bHiB = sb + 2 * TILE_BYTES;
        const uint32_t bLoB = sb + 3 * TILE_BYTES;
#pragma unroll
        for (int k16 = 0; k16 < 4; k16++) {
            const int kb = k16 * 2 + (lane >> 4);
            uint32_t ahi[2][4], alo[2][4];
#pragma unroll
            for (int m = 0; m < 2; m++) {
                const int r = wm * 32 + m * 16 + (lane & 15);
                const uint32_t off = r * 128 + ((kb ^ (r & 7)) << 4);
                LDSM_X4(ahi[m][0], ahi[m][1], ahi[m][2], ahi[m][3], aHiB + off);
                LDSM_X4(alo[m][0], alo[m][1], alo[m][2], alo[m][3], aLoB + off);
            }
            uint32_t bhi[8][2], blo[8][2];
#pragma unroll
            for (int np = 0; np < 4; np++) {
                const int r = wn * 64 + np * 16 + (lane & 15);
                const uint32_t off = r * 128 + ((kb ^ (r & 7)) << 4);
                uint32_t t0, t1, t2, t3;
                LDSM_X4(t0, t1, t2, t3, bHiB + off);
                bhi[np*2][0] = t0; bhi[np*2][1] = t2;
                bhi[np*2+1][0] = t1; bhi[np*2+1][1] = t3;
                LDSM_X4(t0, t1, t2, t3, bLoB + off);
                blo[np*2][0] = t0; blo[np*2][1] = t2;
                blo[np*2+1][0] = t1; blo[np*2+1][1] = t3;
            }
#pragma unroll
            for (int m = 0; m < 2; m++)
#pragma unroll
                for (int n = 0; n < 8; n++) {
                    MMA_BF16(acc[m][n], ahi[m], bhi[n]);
                    MMA_BF16(acc[m][n], alo[m], bhi[n]);
                    MMA_BF16(acc[m][n], ahi[m], blo[n]);
                }
        }
    };

    // ---- 2-stage pipeline
    issue_loads(0);
    for (int it = 0; it < niter; it++) {
        if (it + 1 < niter) { issue_loads(it + 1); CP_WAIT1(); }
        else                { CP_WAIT0(); }
        __syncthreads();
        compute(it & 1);
        __syncthreads();
    }

    // ---------------- Epilogue ----------------
    if (mode == 0) {
        // xg = D + bias (rows m = b*T+t, gate-interleaved cols)
#pragma unroll
        for (int m = 0; m < 2; m++) {
            const int row0 = tileM * 128 + wm * 32 + m * 16 + (lane >> 2);
#pragma unroll
            for (int n = 0; n < 8; n++) {
                const int col = tileN * 128 + wn * 64 + n * 8 + 2 * (lane & 3);
                const float2 bz = *(const float2*)(g_bias + col);
                float2 v0, v1;
                v0.x = acc[m][n][0] + bz.x; v0.y = acc[m][n][1] + bz.y;
                v1.x = acc[m][n][2] + bz.x; v1.y = acc[m][n][3] + bz.y;
                *(float2*)(g_xg + (size_t)row0 * GG + col)       = v0;
                *(float2*)(g_xg + (size_t)(row0 + 8) * GG + col) = v1;
            }
        }
    } else {
        // Fused LSTM cell. Gate-interleaved cols: unit u occupies cols 4u..4u+3
        // (i,f,g,o). Lane pair (l, l^1) jointly holds one unit's 4 gates for
        // rows r0 and r0+8; one shuffle exchange gives each lane a full cell.
        const int odd = lane & 1;
        const int nxt = (t & 1) ^ 1;
        __nv_bfloat16* hsN = g_hs[nxt];
#pragma unroll
        for (int m = 0; m < 2; m++) {
#pragma unroll
            for (int n = 0; n < 8; n++) {
                const float c0 = acc[m][n][0], c1 = acc[m][n][1];
                const float c2 = acc[m][n][2], c3 = acc[m][n][3];
                const float s0 = odd ? c0 : c2;
                const float s1 = odd ? c1 : c3;
                const float rx = __shfl_xor_sync(0xffffffffu, s0, 1);
                const float ry = __shfl_xor_sync(0xffffffffu, s1, 1);
                const float gi = odd ? rx : c0;
                const float gf = odd ? ry : c1;
                const float gg = odd ? c2 : rx;
                const float go = odd ? c3 : ry;
                const int b  = tileM * 128 + wm * 32 + m * 16 + (lane >> 2) + (odd ? 8 : 0);
                const int ug = tileN * 32 + wn * 16 + n * 2 + ((lane & 3) >> 1);

                const float4 xv = *(const float4*)(g_xg + ((size_t)b * TT + t) * GG + 4 * (size_t)ug);
                const float pi = gi + xv.x;
                const float pf = gf + xv.y;
                const float pg = gg + xv.z;
                const float po = go + xv.w;

                const float ig = 1.0f / (1.0f + __expf(-pi));
                const float fg = 1.0f / (1.0f + __expf(-pf));
                const float eg = __expf(-2.0f * fabsf(pg));
                const float tg = copysignf((1.0f - eg) / (1.0f + eg), pg);
                const float og = 1.0f / (1.0f + __expf(-po));

                const size_t ci = (size_t)b * HH + ug;
                const float cn = fg * g_c[ci] + ig * tg;
                const float ec = __expf(-2.0f * fabsf(cn));
                const float th = copysignf((1.0f - ec) / (1.0f + ec), cn);
                const float h  = og * th;
                g_c[ci] = cn;

                const __nv_bfloat16 hhi = __float2bfloat16(h);
                const __nv_bfloat16 hlo = __float2bfloat16(h - __bfloat162float(hhi));
                __nv_bfloat16* hn = hsN + (size_t)b * LDA_R;
                hn[ug] = hhi;
                hn[KSEG_R + ug] = hlo;
                if (out) out[(size_t)b * HH + ug] = h;
            }
        }
    }
}

// ---------------------------------------------------------------------------
// Prep kernels: split fp32 -> (hi, lo) bf16 with gate-interleaved row reorder.
// Reordered row r  <->  original row (r&3)*H + (r>>2).
// ---------------------------------------------------------------------------
__global__ void prep_whh_kernel(const float* __restrict__ W) {
    int idx = blockIdx.x * blockDim.x + threadIdx.x;
    if (idx >= GG * HH) return;
    int r = idx / HH, k = idx - r * HH;
    int orig = (r & 3) * HH + (r >> 2);
    float w = W[(size_t)orig * HH + k];
    __nv_bfloat16 hi = __float2bfloat16(w);
    __nv_bfloat16 lo = __float2bfloat16(w - __bfloat162float(hi));
    g_whh[(size_t)r * LDA_R + k] = hi;
    g_whh[(size_t)r * LDA_R + KSEG_R + k] = lo;
}

__global__ void prep_wih_kernel(const float* __restrict__ W) {
    int idx = blockIdx.x * blockDim.x + threadIdx.x;
    if (idx >= GG * KSEG_X) return;
    int r = idx / KSEG_X, k = idx - r * KSEG_X;
    int orig = (r & 3) * HH + (r >> 2);
    float w = (k < EE) ? W[(size_t)orig * EE + k] : 0.0f;
    __nv_bfloat16 hi = __float2bfloat16(w);
    __nv_bfloat16 lo = __float2bfloat16(w - __bfloat162float(hi));
    g_wih[(size_t)r * LDA_X + k] = hi;
    g_wih[(size_t)r * LDA_X + KSEG_X + k] = lo;
}

__global__ void prep_x_kernel(const float* __restrict__ x) {
    int idx = blockIdx.x * blockDim.x + threadIdx.x;
    if (idx >= BB * TT * KSEG_X) return;
    int m = idx / KSEG_X, k = idx - m * KSEG_X;
    float w = (k < EE) ? x[(size_t)m * EE + k] : 0.0f;
    __nv_bfloat16 hi = __float2bfloat16(w);
    __nv_bfloat16 lo = __float2bfloat16(w - __bfloat162float(hi));
    g_xs[(size_t)m * LDA_X + k] = hi;
    g_xs[(size_t)m * LDA_X + KSEG_X + k] = lo;
}

__global__ void prep_bias_kernel(const float* __restrict__ b_ih,
                                 const float* __restrict__ b_hh) {
    int n = blockIdx.x * blockDim.x + threadIdx.x;
    if (n >= GG) return;
    int orig = (n & 3) * HH + (n >> 2);
    g_bias[n] = b_ih[orig] + b_hh[orig];
}

__global__ void init_state_kernel() {
    int i = blockIdx.x * blockDim.x + threadIdx.x;
    if (i < BB * LDA_R) g_hs[0][i] = __float2bfloat16(0.0f);
    if (i < BB * HH)    g_c[i] = 0.0f;
}

// ---------------------------------------------------------------------------
// Launch
// ---------------------------------------------------------------------------
extern "C" void kernel_launch(void* const* d_in, const int* in_sizes, int n_in,
                              void* d_out, int out_size) {
    const float* x    = (const float*)d_in[0];   // [B, T, E]
    const float* W_ih = (const float*)d_in[1];   // [4H, E]
    const float* W_hh = (const float*)d_in[2];   // [4H, H]
    const float* b_ih = (const float*)d_in[3];   // [4H]
    const float* b_hh = (const float*)d_in[4];   // [4H]
    float* out = (float*)d_out;                  // [B, H]

    static int smem_set = 0;
    if (!smem_set) {
        cudaFuncSetAttribute(gemm_split_kernel,
                             cudaFuncAttributeMaxDynamicSharedMemorySize, SMEM_DYN);
        smem_set = 1;
    }

    __nv_bfloat16 *xs_p, *wih_p, *whh_p, *hs_p;
    cudaGetSymbolAddress((void**)&xs_p,  g_xs);
    cudaGetSymbolAddress((void**)&wih_p, g_wih);
    cudaGetSymbolAddress((void**)&whh_p, g_whh);
    cudaGetSymbolAddress((void**)&hs_p,  g_hs);

    // Prep
    prep_whh_kernel<<<(GG * HH + 255) / 256, 256>>>(W_hh);
    prep_wih_kernel<<<(GG * KSEG_X + 255) / 256, 256>>>(W_ih);
    prep_x_kernel<<<(BB * TT * KSEG_X + 255) / 256, 256>>>(x);
    prep_bias_kernel<<<(GG + 255) / 256, 256>>>(b_ih, b_hh);
    init_state_kernel<<<(BB * LDA_R + 255) / 256, 256>>>();

    // Phase 1: xg = split(x) @ split(W_ih)^T + bias   (M=32768, K=2*320)
    {
        dim3 grid(GG / 128, (BB * TT) / 128);    // 64 x 256
        gemm_split_kernel<<<grid, 256, SMEM_DYN>>>(
            xs_p, wih_p, LDA_X, KSEG_X, KSEG_X / 64, /*mode=*/0, 0, nullptr);
    }

    // Phase 2: recurrence with fused LSTM cell epilogue
    for (int t = 0; t < TT; t++) {
        dim3 grid(GG / 128, BB / 128);           // 64 x 2
        const __nv_bfloat16* Acur = hs_p + (size_t)(t & 1) * BB * LDA_R;
        gemm_split_kernel<<<grid, 256, SMEM_DYN>>>(
            Acur, whh_p, LDA_R, KSEG_R, KSEG_R / 64, /*mode=*/1, t,
            (t == TT - 1) ? out : nullptr);
    }
}

// round 8
// speedup vs baseline: 5.0685x; 1.2523x over previous
#include <cuda_runtime.h>
#include <cuda_fp16.h>
#include <stdint.h>
#include <math.h>

// ---------------------------------------------------------------------------
// Problem constants
// ---------------------------------------------------------------------------
#define BB 256
#define TT 128
#define EE 300
#define HH 2048
#define GG 8192      // 4*H

#define KSEG_R 2048  // recurrence K segment (h hi / lo halves)
#define KSEG_X 320   // phase-1 K segment (300 padded to 320)
#define LDA_R 4096   // 2*KSEG_R  (row stride of split h)
#define LDA_X 640    // 2*KSEG_X

#define TILE_BYTES 16384            // 128 rows x 128 bytes (64 fp16)

// ---------------------------------------------------------------------------
// Device scratch (no allocations allowed)
// ---------------------------------------------------------------------------
__device__ float                 g_xg[(size_t)BB * TT * GG];    // [B*T][8192] gate-interleaved fp32
__device__ __align__(16) __half  g_whh[(size_t)GG * HH];        // PLAIN fp16, rows gate-reordered
__device__ __align__(16) __half  g_wih[(size_t)GG * LDA_X];     // split fp16 [hi | lo], K padded
__device__ __align__(16) __half  g_xs[(size_t)BB * TT * LDA_X]; // split fp16 [hi | lo], K padded
__device__ __align__(16) __half  g_hs[2][(size_t)BB * LDA_R];   // ping-pong split h: [hi | lo]
__device__ float                 g_c[(size_t)BB * HH];
__device__ float                 g_bias[GG];                     // reordered b_ih + b_hh

// ---------------------------------------------------------------------------
// PTX helpers (baseline ISA: cp.async / ldmatrix / mma.sync -- sm_80+)
// ---------------------------------------------------------------------------
__device__ __forceinline__ uint32_t smem_u32(const void* p) {
    uint32_t a;
    asm("{ .reg .u64 t; cvta.to.shared.u64 t, %1; cvt.u32.u64 %0, t; }" : "=r"(a) : "l"(p));
    return a;
}

#define CP_ASYNC16(sa, ga) \
    asm volatile("cp.async.cg.shared.global [%0], [%1], 16;" :: "r"(sa), "l"(ga))
#define CP_COMMIT() asm volatile("cp.async.commit_group;")
#define CP_WAIT1()  asm volatile("cp.async.wait_group 1;")

#define LDSM_X4(r0, r1, r2, r3, addr) \
    asm volatile("ldmatrix.sync.aligned.m8n8.x4.shared.b16 {%0,%1,%2,%3}, [%4];" \
                 : "=r"(r0), "=r"(r1), "=r"(r2), "=r"(r3) : "r"(addr))

#define MMA_F16(d, a, b) \
    asm volatile("mma.sync.aligned.m16n8k16.row.col.f32.f16.f16.f32 " \
                 "{%0,%1,%2,%3}, {%4,%5,%6,%7}, {%8,%9}, {%0,%1,%2,%3};" \
                 : "+f"((d)[0]), "+f"((d)[1]), "+f"((d)[2]), "+f"((d)[3]) \
                 : "r"((a)[0]), "r"((a)[1]), "r"((a)[2]), "r"((a)[3]), \
                   "r"((b)[0]), "r"((b)[1]))

// ---------------------------------------------------------------------------
// Unified split-fp16 HMMA GEMM, 3-stage cp.async pipeline.
//  TERMS==3 (phase 1): tiles {Ahi, Alo, Bhi, Blo}; acc = Ahi*Bhi + Alo*Bhi + Ahi*Blo
//  TERMS==2 (recurrence): tiles {Ahi, Alo, B};     acc = Ahi*B + Alo*B
//  mode 0: write g_xg (+bias).   mode 1: fused LSTM cell epilogue at step t.
//  8 warps: 4 (M) x 2 (N); CTA tile 128x128; warp tile 32x64; BK=64.
// ---------------------------------------------------------------------------
template<int TERMS>
__global__ void __launch_bounds__(256, 1)
gemm_kernel(const __half* __restrict__ A, const __half* __restrict__ Bw,
            int lda, int ldb, int ksegA, int ksegB, int niter,
            int mode, int t, float* __restrict__ out)
{
    constexpr int NT = (TERMS == 3) ? 4 : 3;   // tiles per stage
    constexpr int STAGE_BYTES = NT * TILE_BYTES;

    extern __shared__ char smem[];
    const int tid  = threadIdx.x;
    const int lane = tid & 31;
    const int wid  = tid >> 5;
    const int wm   = wid >> 1;      // 0..3  (M direction)
    const int wn   = wid & 1;       // 0..1  (N direction)
    const int tileN = blockIdx.x;
    const int tileM = blockIdx.y;
    const uint32_t sbase = smem_u32(smem);

    const __half* aBase = A  + (size_t)(tileM * 128) * lda;
    const __half* bBase = Bw + (size_t)(tileN * 128) * ldb;

    float acc[2][8][4];
#pragma unroll
    for (int m = 0; m < 2; m++)
#pragma unroll
        for (int n = 0; n < 8; n++)
#pragma unroll
            for (int v = 0; v < 4; v++) acc[m][n][v] = 0.0f;

    // ---- async stage loader; ALWAYS commits exactly one group (empty ok)
    auto issue = [&](int it) {
        if (it < niter) {
            const int k0 = it * 64;
            const uint32_t sb = sbase + (it % 3) * STAGE_BYTES;
#pragma unroll
            for (int s = 0; s < NT * 4; s++) {
                const int linear = tid + s * 256;     // 0 .. NT*1024-1
                const int tile = linear >> 10;        // 0..NT-1
                const int rem  = linear & 1023;
                const int r    = rem >> 3;            // 0..127
                const int kb   = rem & 7;             // 0..7 (16B blocks)
                const __half* g;
                if (tile == 0)      g = aBase + (size_t)r * lda + k0 + kb * 8;
                else if (tile == 1) g = aBase + (size_t)r * lda + ksegA + k0 + kb * 8;
                else if (tile == 2) g = bBase + (size_t)r * ldb + k0 + kb * 8;
                else                g = bBase + (size_t)r * ldb + ksegB + k0 + kb * 8;
                const uint32_t sa = sb + tile * TILE_BYTES + r * 128 + ((kb ^ (r & 7)) << 4);
                CP_ASYNC16(sa, g);
            }
        }
        CP_COMMIT();
    };

    // ---- compute one 64-wide K chunk from stage buf
    auto compute = [&](int buf) {
        const uint32_t sb   = sbase + buf * STAGE_BYTES;
        const uint32_t aHiB = sb;
        const uint32_t aLoB = sb + TILE_BYTES;
        const uint32_t bHiB = sb + 2 * TILE_BYTES;
        const uint32_t bLoB = sb + 3 * TILE_BYTES;   // only valid for TERMS==3
#pragma unroll
        for (int k16 = 0; k16 < 4; k16++) {
            const int kb = k16 * 2 + (lane >> 4);
            uint32_t ahi[2][4], alo[2][4];
#pragma unroll
            for (int m = 0; m < 2; m++) {
                const int r = wm * 32 + m * 16 + (lane & 15);
                const uint32_t off = r * 128 + ((kb ^ (r & 7)) << 4);
                LDSM_X4(ahi[m][0], ahi[m][1], ahi[m][2], ahi[m][3], aHiB + off);
                LDSM_X4(alo[m][0], alo[m][1], alo[m][2], alo[m][3], aLoB + off);
            }
            uint32_t bhi[8][2], blo[8][2];
#pragma unroll
            for (int np = 0; np < 4; np++) {
                const int r = wn * 64 + np * 16 + (lane & 15);
                const uint32_t off = r * 128 + ((kb ^ (r & 7)) << 4);
                uint32_t t0, t1, t2, t3;
                LDSM_X4(t0, t1, t2, t3, bHiB + off);
                bhi[np*2][0] = t0; bhi[np*2][1] = t2;
                bhi[np*2+1][0] = t1; bhi[np*2+1][1] = t3;
                if (TERMS == 3) {
                    LDSM_X4(t0, t1, t2, t3, bLoB + off);
                    blo[np*2][0] = t0; blo[np*2][1] = t2;
                    blo[np*2+1][0] = t1; blo[np*2+1][1] = t3;
                }
            }
#pragma unroll
            for (int m = 0; m < 2; m++)
#pragma unroll
                for (int n = 0; n < 8; n++) {
                    MMA_F16(acc[m][n], ahi[m], bhi[n]);
                    MMA_F16(acc[m][n], alo[m], bhi[n]);
                    if (TERMS == 3) MMA_F16(acc[m][n], ahi[m], blo[n]);
                }
        }
    };

    // ---- 3-stage pipeline: one sync + one (possibly empty) commit per iter
    issue(0);
    issue(1);
    for (int it = 0; it < niter; it++) {
        CP_WAIT1();            // groups 0..it complete -> buffer it%3 ready
        __syncthreads();       // all warps done with buffer (it-1)%3
        issue(it + 2);         // refill buffer (it+2)%3 == (it-1)%3
        compute(it % 3);
    }

    // ---------------- Epilogue ----------------
    if (mode == 0) {
        // xg = D + bias (rows m = b*T+t, gate-interleaved cols)
#pragma unroll
        for (int m = 0; m < 2; m++) {
            const int row0 = tileM * 128 + wm * 32 + m * 16 + (lane >> 2);
#pragma unroll
            for (int n = 0; n < 8; n++) {
                const int col = tileN * 128 + wn * 64 + n * 8 + 2 * (lane & 3);
                const float2 bz = *(const float2*)(g_bias + col);
                float2 v0, v1;
                v0.x = acc[m][n][0] + bz.x; v0.y = acc[m][n][1] + bz.y;
                v1.x = acc[m][n][2] + bz.x; v1.y = acc[m][n][3] + bz.y;
                *(float2*)(g_xg + (size_t)row0 * GG + col)       = v0;
                *(float2*)(g_xg + (size_t)(row0 + 8) * GG + col) = v1;
            }
        }
    } else {
        // Fused LSTM cell. Gate-interleaved cols: unit u occupies cols 4u..4u+3
        // (i,f,g,o). Lane pair (l, l^1) jointly holds one unit's 4 gates for
        // rows r0 and r0+8; one shuffle exchange gives each lane a full cell.
        const int odd = lane & 1;
        const int nxt = (t & 1) ^ 1;
        __half* hsN = g_hs[nxt];
#pragma unroll
        for (int m = 0; m < 2; m++) {
#pragma unroll
            for (int n = 0; n < 8; n++) {
                const float c0 = acc[m][n][0], c1 = acc[m][n][1];
                const float c2 = acc[m][n][2], c3 = acc[m][n][3];
                const float s0 = odd ? c0 : c2;
                const float s1 = odd ? c1 : c3;
                const float rx = __shfl_xor_sync(0xffffffffu, s0, 1);
                const float ry = __shfl_xor_sync(0xffffffffu, s1, 1);
                const float gi = odd ? rx : c0;
                const float gf = odd ? ry : c1;
                const float gg = odd ? c2 : rx;
                const float go = odd ? c3 : ry;
                const int b  = tileM * 128 + wm * 32 + m * 16 + (lane >> 2) + (odd ? 8 : 0);
                const int ug = tileN * 32 + wn * 16 + n * 2 + ((lane & 3) >> 1);

                const float4 xv = *(const float4*)(g_xg + ((size_t)b * TT + t) * GG + 4 * (size_t)ug);
                const float pi = gi + xv.x;
                const float pf = gf + xv.y;
                const float pg = gg + xv.z;
                const float po = go + xv.w;

                const float ig = 1.0f / (1.0f + __expf(-pi));
                const float fg = 1.0f / (1.0f + __expf(-pf));
                const float eg = __expf(-2.0f * fabsf(pg));
                const float tg = copysignf((1.0f - eg) / (1.0f + eg), pg);
                const float og = 1.0f / (1.0f + __expf(-po));

                const size_t ci = (size_t)b * HH + ug;
                const float cn = fg * g_c[ci] + ig * tg;
                const float ec = __expf(-2.0f * fabsf(cn));
                const float th = copysignf((1.0f - ec) / (1.0f + ec), cn);
                const float h  = og * th;
                g_c[ci] = cn;

                const __half hhi = __float2half(h);
                const __half hlo = __float2half(h - __half2float(hhi));
                __half* hn = hsN + (size_t)b * LDA_R;
                hn[ug] = hhi;
                hn[KSEG_R + ug] = hlo;
                if (out) out[(size_t)b * HH + ug] = h;
            }
        }
    }
}

// ---------------------------------------------------------------------------
// Prep kernels.  Reordered row r  <->  original row (r&3)*H + (r>>2).
// ---------------------------------------------------------------------------
__global__ void prep_whh_kernel(const float* __restrict__ W) {
    int idx = blockIdx.x * blockDim.x + threadIdx.x;
    if (idx >= GG * HH) return;
    int r = idx / HH, k = idx - r * HH;
    int orig = (r & 3) * HH + (r >> 2);
    g_whh[(size_t)r * HH + k] = __float2half(W[(size_t)orig * HH + k]);
}

__global__ void prep_wih_kernel(const float* __restrict__ W) {
    int idx = blockIdx.x * blockDim.x + threadIdx.x;
    if (idx >= GG * KSEG_X) return;
    int r = idx / KSEG_X, k = idx - r * KSEG_X;
    int orig = (r & 3) * HH + (r >> 2);
    float w = (k < EE) ? W[(size_t)orig * EE + k] : 0.0f;
    __half hi = __float2half(w);
    __half lo = __float2half(w - __half2float(hi));
    g_wih[(size_t)r * LDA_X + k] = hi;
    g_wih[(size_t)r * LDA_X + KSEG_X + k] = lo;
}

__global__ void prep_x_kernel(const float* __restrict__ x) {
    int idx = blockIdx.x * blockDim.x + threadIdx.x;
    if (idx >= BB * TT * KSEG_X) return;
    int m = idx / KSEG_X, k = idx - m * KSEG_X;
    float w = (k < EE) ? x[(size_t)m * EE + k] : 0.0f;
    __half hi = __float2half(w);
    __half lo = __float2half(w - __half2float(hi));
    g_xs[(size_t)m * LDA_X + k] = hi;
    g_xs[(size_t)m * LDA_X + KSEG_X + k] = lo;
}

__global__ void prep_bias_kernel(const float* __restrict__ b_ih,
                                 const float* __restrict__ b_hh) {
    int n = blockIdx.x * blockDim.x + threadIdx.x;
    if (n >= GG) return;
    int orig = (n & 3) * HH + (n >> 2);
    g_bias[n] = b_ih[orig] + b_hh[orig];
}

__global__ void init_state_kernel() {
    int i = blockIdx.x * blockDim.x + threadIdx.x;
    if (i < BB * LDA_R) g_hs[0][i] = __float2half(0.0f);
    if (i < BB * HH)    g_c[i] = 0.0f;
}

// ---------------------------------------------------------------------------
// Launch
// ---------------------------------------------------------------------------
#define SMEM_T2 (3 * 3 * TILE_BYTES)   // 147456
#define SMEM_T3 (3 * 4 * TILE_BYTES)   // 196608

extern "C" void kernel_launch(void* const* d_in, const int* in_sizes, int n_in,
                              void* d_out, int out_size) {
    const float* x    = (const float*)d_in[0];   // [B, T, E]
    const float* W_ih = (const float*)d_in[1];   // [4H, E]
    const float* W_hh = (const float*)d_in[2];   // [4H, H]
    const float* b_ih = (const float*)d_in[3];   // [4H]
    const float* b_hh = (const float*)d_in[4];   // [4H]
    float* out = (float*)d_out;                  // [B, H]

    static int smem_set = 0;
    if (!smem_set) {
        cudaFuncSetAttribute(gemm_kernel<2>,
                             cudaFuncAttributeMaxDynamicSharedMemorySize, SMEM_T2);
        cudaFuncSetAttribute(gemm_kernel<3>,
                             cudaFuncAttributeMaxDynamicSharedMemorySize, SMEM_T3);
        smem_set = 1;
    }

    __half *xs_p, *wih_p, *whh_p, *hs_p;
    cudaGetSymbolAddress((void**)&xs_p,  g_xs);
    cudaGetSymbolAddress((void**)&wih_p, g_wih);
    cudaGetSymbolAddress((void**)&whh_p, g_whh);
    cudaGetSymbolAddress((void**)&hs_p,  g_hs);

    // Prep
    prep_whh_kernel<<<(GG * HH + 255) / 256, 256>>>(W_hh);
    prep_wih_kernel<<<(GG * KSEG_X + 255) / 256, 256>>>(W_ih);
    prep_x_kernel<<<(BB * TT * KSEG_X + 255) / 256, 256>>>(x);
    prep_bias_kernel<<<(GG + 255) / 256, 256>>>(b_ih, b_hh);
    init_state_kernel<<<(BB * LDA_R + 255) / 256, 256>>>();

    // Phase 1 (3-term fp16): xg = split(x) @ split(W_ih)^T + bias
    {
        dim3 grid(GG / 128, (BB * TT) / 128);    // 64 x 256
        gemm_kernel<3><<<grid, 256, SMEM_T3>>>(
            xs_p, wih_p, LDA_X, LDA_X, KSEG_X, KSEG_X, KSEG_X / 64,
            /*mode=*/0, 0, nullptr);
    }

    // Phase 2 (2-term fp16): recurrence with fused LSTM cell epilogue
    for (int t = 0; t < TT; t++) {
        dim3 grid(GG / 128, BB / 128);           // 64 x 2
        const __half* Acur = hs_p + (size_t)(t & 1) * BB * LDA_R;
        gemm_kernel<2><<<grid, 256, SMEM_T2>>>(
            Acur, whh_p, LDA_R, HH, KSEG_R, 0, KSEG_R / 64,
            /*mode=*/1, t, (t == TT - 1) ? out : nullptr);
    }
}

// round 11
// speedup vs baseline: 7.5538x; 1.4903x over previous
#include <cuda_runtime.h>
#include <cuda_fp16.h>
#include <stdint.h>
#include <math.h>

// ---------------------------------------------------------------------------
// Problem constants
// ---------------------------------------------------------------------------
#define BB 256
#define TT 128
#define EE 300
#define HH 2048
#define GG 8192      // 4*H

#define KSEG_X 320   // phase-1 K segment (300 padded to 320)
#define LDA_X 640    // 2*KSEG_X (split x row stride)

#define TILE_BYTES 16384            // 128 rows x 128 bytes (64 fp16)

// ---------------------------------------------------------------------------
// Device scratch (no allocations allowed)
// ---------------------------------------------------------------------------
__device__ float                 g_xg[(size_t)BB * TT * GG];    // [B*T][8192] gate-interleaved fp32
__device__ __align__(16) __half  g_whh[(size_t)GG * HH];        // plain fp16, rows gate-reordered
__device__ __align__(16) __half  g_wih[(size_t)GG * KSEG_X];    // plain fp16, rows reordered, K padded
__device__ __align__(16) __half  g_xs[(size_t)BB * TT * LDA_X]; // split fp16 [hi | lo], K padded
__device__ __align__(16) __half  g_hs[2][(size_t)BB * HH];      // ping-pong plain fp16 h
__device__ float                 g_c[(size_t)BB * HH];
__device__ float                 g_bias[GG];                     // reordered b_ih + b_hh

// ---------------------------------------------------------------------------
// PTX helpers (baseline ISA: cp.async / ldmatrix / mma.sync -- sm_80+)
// ---------------------------------------------------------------------------
__device__ __forceinline__ uint32_t smem_u32(const void* p) {
    uint32_t a;
    asm("{ .reg .u64 t; cvta.to.shared.u64 t, %1; cvt.u32.u64 %0, t; }" : "=r"(a) : "l"(p));
    return a;
}

#define CP_ASYNC16(sa, ga) \
    asm volatile("cp.async.cg.shared.global [%0], [%1], 16;" :: "r"(sa), "l"(ga))
#define CP_COMMIT() asm volatile("cp.async.commit_group;")
#define CP_WAIT1()  asm volatile("cp.async.wait_group 1;")

#define LDSM_X4(r0, r1, r2, r3, addr) \
    asm volatile("ldmatrix.sync.aligned.m8n8.x4.shared.b16 {%0,%1,%2,%3}, [%4];" \
                 : "=r"(r0), "=r"(r1), "=r"(r2), "=r"(r3) : "r"(addr))

#define MMA_F16(d, a, b) \
    asm volatile("mma.sync.aligned.m16n8k16.row.col.f32.f16.f16.f32 " \
                 "{%0,%1,%2,%3}, {%4,%5,%6,%7}, {%8,%9}, {%0,%1,%2,%3};" \
                 : "+f"((d)[0]), "+f"((d)[1]), "+f"((d)[2]), "+f"((d)[3]) \
                 : "r"((a)[0]), "r"((a)[1]), "r"((a)[2]), "r"((a)[3]), \
                   "r"((b)[0]), "r"((b)[1]))

// ---------------------------------------------------------------------------
// Unified fp16 HMMA GEMM, 3-stage cp.async pipeline.
//  TERMS==2 (phase 1): tiles {Ahi, Alo, B}; acc = Ahi*B + Alo*B  (x split)
//  TERMS==1 (recurrence): tiles {A, B};     acc = A*B            (h plain)
//  mode 0: write g_xg (+bias).   mode 1: fused LSTM cell epilogue at step t.
//  8 warps: 4 (M) x 2 (N); CTA tile 128x128; warp tile 32x64; BK=64.
// ---------------------------------------------------------------------------
template<int TERMS>
__global__ void __launch_bounds__(256, 1)
gemm_kernel(const __half* __restrict__ A, const __half* __restrict__ Bw,
            int lda, int ldb, int ksegA, int niter,
            int mode, int t, float* __restrict__ out)
{
    constexpr int NT = TERMS + 1;              // tiles per stage
    constexpr int STAGE_BYTES = NT * TILE_BYTES;

    extern __shared__ char smem[];
    const int tid  = threadIdx.x;
    const int lane = tid & 31;
    const int wid  = tid >> 5;
    const int wm   = wid >> 1;      // 0..3  (M direction)
    const int wn   = wid & 1;       // 0..1  (N direction)
    const int tileN = blockIdx.x;
    const int tileM = blockIdx.y;
    const uint32_t sbase = smem_u32(smem);

    const __half* aBase = A  + (size_t)(tileM * 128) * lda;
    const __half* bBase = Bw + (size_t)(tileN * 128) * ldb;

    float acc[2][8][4];
#pragma unroll
    for (int m = 0; m < 2; m++)
#pragma unroll
        for (int n = 0; n < 8; n++)
#pragma unroll
            for (int v = 0; v < 4; v++) acc[m][n][v] = 0.0f;

    // ---- async stage loader; ALWAYS commits exactly one group (empty ok)
    auto issue = [&](int it) {
        if (it < niter) {
            const int k0 = it * 64;
            const uint32_t sb = sbase + (it % 3) * STAGE_BYTES;
#pragma unroll
            for (int s = 0; s < NT * 4; s++) {
                const int linear = tid + s * 256;     // 0 .. NT*1024-1
                const int tile = linear >> 10;        // 0..NT-1
                const int rem  = linear & 1023;
                const int r    = rem >> 3;            // 0..127
                const int kb   = rem & 7;             // 0..7 (16B blocks)
                const __half* g;
                if (TERMS == 1) {
                    g = (tile == 0) ? aBase + (size_t)r * lda + k0 + kb * 8
                                    : bBase + (size_t)r * ldb + k0 + kb * 8;
                } else {
                    if (tile == 0)      g = aBase + (size_t)r * lda + k0 + kb * 8;
                    else if (tile == 1) g = aBase + (size_t)r * lda + ksegA + k0 + kb * 8;
                    else                g = bBase + (size_t)r * ldb + k0 + kb * 8;
                }
                const uint32_t sa = sb + tile * TILE_BYTES + r * 128 + ((kb ^ (r & 7)) << 4);
                CP_ASYNC16(sa, g);
            }
        }
        CP_COMMIT();
    };

    // ---- compute one 64-wide K chunk from stage buf
    auto compute = [&](int buf) {
        const uint32_t sb  = sbase + buf * STAGE_BYTES;
        const uint32_t aB  = sb;
        const uint32_t a2B = sb + TILE_BYTES;                 // Alo (TERMS==2)
        const uint32_t bB  = sb + (NT - 1) * TILE_BYTES;      // B tile is last
#pragma unroll
        for (int k16 = 0; k16 < 4; k16++) {
            const int kb = k16 * 2 + (lane >> 4);
            uint32_t a1[2][4], a2[2][4];
#pragma unroll
            for (int m = 0; m < 2; m++) {
                const int r = wm * 32 + m * 16 + (lane & 15);
                const uint32_t off = r * 128 + ((kb ^ (r & 7)) << 4);
                LDSM_X4(a1[m][0], a1[m][1], a1[m][2], a1[m][3], aB + off);
                if (TERMS == 2)
                    LDSM_X4(a2[m][0], a2[m][1], a2[m][2], a2[m][3], a2B + off);
            }
            uint32_t bf[8][2];
#pragma unroll
            for (int np = 0; np < 4; np++) {
                const int r = wn * 64 + np * 16 + (lane & 15);
                const uint32_t off = r * 128 + ((kb ^ (r & 7)) << 4);
                uint32_t t0, t1, t2, t3;
                LDSM_X4(t0, t1, t2, t3, bB + off);
                bf[np*2][0] = t0; bf[np*2][1] = t2;
                bf[np*2+1][0] = t1; bf[np*2+1][1] = t3;
            }
#pragma unroll
            for (int m = 0; m < 2; m++)
#pragma unroll
                for (int n = 0; n < 8; n++) {
                    MMA_F16(acc[m][n], a1[m], bf[n]);
                    if (TERMS == 2) MMA_F16(acc[m][n], a2[m], bf[n]);
                }
        }
    };

    // ---- 3-stage pipeline: one sync + one (possibly empty) commit per iter
    issue(0);
    issue(1);
    for (int it = 0; it < niter; it++) {
        CP_WAIT1();            // groups 0..it complete -> buffer it%3 ready
        __syncthreads();       // all warps done with buffer (it-1)%3
        issue(it + 2);         // refill buffer (it+2)%3 == (it-1)%3
        compute(it % 3);
    }

    // ---------------- Epilogue ----------------
    if (mode == 0) {
        // xg = D + bias (rows m = b*T+t, gate-interleaved cols)
#pragma unroll
        for (int m = 0; m < 2; m++) {
            const int row0 = tileM * 128 + wm * 32 + m * 16 + (lane >> 2);
#pragma unroll
            for (int n = 0; n < 8; n++) {
                const int col = tileN * 128 + wn * 64 + n * 8 + 2 * (lane & 3);
                const float2 bz = *(const float2*)(g_bias + col);
                float2 v0, v1;
                v0.x = acc[m][n][0] + bz.x; v0.y = acc[m][n][1] + bz.y;
                v1.x = acc[m][n][2] + bz.x; v1.y = acc[m][n][3] + bz.y;
                *(float2*)(g_xg + (size_t)row0 * GG + col)       = v0;
                *(float2*)(g_xg + (size_t)(row0 + 8) * GG + col) = v1;
            }
        }
    } else {
        // Fused LSTM cell. Gate-interleaved cols: unit u occupies cols 4u..4u+3
        // (i,f,g,o). Lane pair (l, l^1) jointly holds one unit's 4 gates for
        // rows r0 and r0+8; one shuffle exchange gives each lane a full cell.
        const int odd = lane & 1;
        const int nxt = (t & 1) ^ 1;
        __half* hsN = g_hs[nxt];
#pragma unroll
        for (int m = 0; m < 2; m++) {
#pragma unroll
            for (int n = 0; n < 8; n++) {
                const float c0 = acc[m][n][0], c1 = acc[m][n][1];
                const float c2 = acc[m][n][2], c3 = acc[m][n][3];
                const float s0 = odd ? c0 : c2;
                const float s1 = odd ? c1 : c3;
                const float rx = __shfl_xor_sync(0xffffffffu, s0, 1);
                const float ry = __shfl_xor_sync(0xffffffffu, s1, 1);
                const float gi = odd ? rx : c0;
                const float gf = odd ? ry : c1;
                const float gg = odd ? c2 : rx;
                const float go = odd ? c3 : ry;
                const int b  = tileM * 128 + wm * 32 + m * 16 + (lane >> 2) + (odd ? 8 : 0);
                const int ug = tileN * 32 + wn * 16 + n * 2 + ((lane & 3) >> 1);

                const float4 xv = *(const float4*)(g_xg + ((size_t)b * TT + t) * GG + 4 * (size_t)ug);
                const float pi = gi + xv.x;
                const float pf = gf + xv.y;
                const float pg = gg + xv.z;
                const float po = go + xv.w;

                const float ig = 1.0f / (1.0f + __expf(-pi));
                const float fg = 1.0f / (1.0f + __expf(-pf));
                const float eg = __expf(-2.0f * fabsf(pg));
                const float tg = copysignf((1.0f - eg) / (1.0f + eg), pg);
                const float og = 1.0f / (1.0f + __expf(-po));

                const size_t ci = (size_t)b * HH + ug;
                const float cn = fg * g_c[ci] + ig * tg;
                const float ec = __expf(-2.0f * fabsf(cn));
                const float th = copysignf((1.0f - ec) / (1.0f + ec), cn);
                const float h  = og * th;
                g_c[ci] = cn;

                hsN[ci] = __float2half(h);
                if (out) out[ci] = h;
            }
        }
    }
}

// ---------------------------------------------------------------------------
// Prep kernels.  Reordered row r  <->  original row (r&3)*H + (r>>2).
// ---------------------------------------------------------------------------
__global__ void prep_whh_kernel(const float* __restrict__ W) {
    int idx = blockIdx.x * blockDim.x + threadIdx.x;
    if (idx >= GG * HH) return;
    int r = idx / HH, k = idx - r * HH;
    int orig = (r & 3) * HH + (r >> 2);
    g_whh[(size_t)r * HH + k] = __float2half(W[(size_t)orig * HH + k]);
}

__global__ void prep_wih_kernel(const float* __restrict__ W) {
    int idx = blockIdx.x * blockDim.x + threadIdx.x;
    if (idx >= GG * KSEG_X) return;
    int r = idx / KSEG_X, k = idx - r * KSEG_X;
    int orig = (r & 3) * HH + (r >> 2);
    float w = (k < EE) ? W[(size_t)orig * EE + k] : 0.0f;
    g_wih[(size_t)r * KSEG_X + k] = __float2half(w);
}

__global__ void prep_x_kernel(const float* __restrict__ x) {
    int idx = blockIdx.x * blockDim.x + threadIdx.x;
    if (idx >= BB * TT * KSEG_X) return;
    int m = idx / KSEG_X, k = idx - m * KSEG_X;
    float w = (k < EE) ? x[(size_t)m * EE + k] : 0.0f;
    __half hi = __float2half(w);
    __half lo = __float2half(w - __half2float(hi));
    g_xs[(size_t)m * LDA_X + k] = hi;
    g_xs[(size_t)m * LDA_X + KSEG_X + k] = lo;
}

__global__ void prep_bias_kernel(const float* __restrict__ b_ih,
                                 const float* __restrict__ b_hh) {
    int n = blockIdx.x * blockDim.x + threadIdx.x;
    if (n >= GG) return;
    int orig = (n & 3) * HH + (n >> 2);
    g_bias[n] = b_ih[orig] + b_hh[orig];
}

__global__ void init_state_kernel() {
    int i = blockIdx.x * blockDim.x + threadIdx.x;
    if (i < BB * HH) { g_hs[0][i] = __float2half(0.0f); g_c[i] = 0.0f; }
}

// ---------------------------------------------------------------------------
// Launch
// ---------------------------------------------------------------------------
#define SMEM_T1 (3 * 2 * TILE_BYTES)   //  98304
#define SMEM_T2 (3 * 3 * TILE_BYTES)   // 147456

extern "C" void kernel_launch(void* const* d_in, const int* in_sizes, int n_in,
                              void* d_out, int out_size) {
    const float* x    = (const float*)d_in[0];   // [B, T, E]
    const float* W_ih = (const float*)d_in[1];   // [4H, E]
    const float* W_hh = (const float*)d_in[2];   // [4H, H]
    const float* b_ih = (const float*)d_in[3];   // [4H]
    const float* b_hh = (const float*)d_in[4];   // [4H]
    float* out = (float*)d_out;                  // [B, H]

    cudaFuncSetAttribute(gemm_kernel<1>,
                         cudaFuncAttributeMaxDynamicSharedMemorySize, SMEM_T1);
    cudaFuncSetAttribute(gemm_kernel<2>,
                         cudaFuncAttributeMaxDynamicSharedMemorySize, SMEM_T2);

    __half *xs_p, *wih_p, *whh_p, *hs_p;
    cudaGetSymbolAddress((void**)&xs_p,  g_xs);
    cudaGetSymbolAddress((void**)&wih_p, g_wih);
    cudaGetSymbolAddress((void**)&whh_p, g_whh);
    cudaGetSymbolAddress((void**)&hs_p,  g_hs);

    // Prep
    prep_whh_kernel<<<(GG * HH + 255) / 256, 256>>>(W_hh);
    prep_wih_kernel<<<(GG * KSEG_X + 255) / 256, 256>>>(W_ih);
    prep_x_kernel<<<(BB * TT * KSEG_X + 255) / 256, 256>>>(x);
    prep_bias_kernel<<<(GG + 255) / 256, 256>>>(b_ih, b_hh);
    init_state_kernel<<<(BB * HH + 255) / 256, 256>>>();

    // Phase 1 (2-term: x split, W_ih plain fp16): xg = x @ W_ih^T + bias
    {
        dim3 grid(GG / 128, (BB * TT) / 128);    // 64 x 256
        gemm_kernel<2><<<grid, 256, SMEM_T2>>>(
            xs_p, wih_p, LDA_X, KSEG_X, KSEG_X, KSEG_X / 64,
            /*mode=*/0, 0, nullptr);
    }

    // Phase 2 (1-term: h plain fp16, W_hh plain fp16): fused LSTM recurrence
    for (int t = 0; t < TT; t++) {
        dim3 grid(GG / 128, BB / 128);           // 64 x 2
        const __half* Acur = hs_p + (size_t)(t & 1) * BB * HH;
        gemm_kernel<1><<<grid, 256, SMEM_T1>>>(
            Acur, whh_p, HH, HH, 0, HH / 64,
            /*mode=*/1, t, (t == TT - 1) ? out : nullptr);
    }
}

// round 12
// speedup vs baseline: 9.6829x; 1.2819x over previous
#include <cuda_runtime.h>
#include <cuda_fp16.h>
#include <stdint.h>
#include <math.h>

// ---------------------------------------------------------------------------
// Problem constants
// ---------------------------------------------------------------------------
#define BB 256
#define TT 128
#define EE 300
#define HH 2048
#define GG 8192      // 4*H

#define KSEG_X 320   // phase-1 K (300 padded to 320)

#define TILE_BYTES 16384            // 128 rows x 128 bytes (64 fp16)
#define STAGE_BYTES (2 * TILE_BYTES)
#define SMEM_SZ (3 * STAGE_BYTES)   // 98304 (both kernels)

#define NBLK 128                    // persistent grid size (2 x 64)

// ---------------------------------------------------------------------------
// Device scratch (no allocations allowed)
// ---------------------------------------------------------------------------
__device__ __align__(16) __half  g_xg[(size_t)BB * TT * GG];    // fp16 gate-interleaved xg (+bias)
__device__ __align__(16) __half  g_whh[(size_t)GG * HH];        // plain fp16, rows gate-reordered
__device__ __align__(16) __half  g_wih[(size_t)GG * KSEG_X];    // plain fp16, rows reordered, K padded
__device__ __align__(16) __half  g_xs[(size_t)BB * TT * KSEG_X];// plain fp16 x, K padded
__device__ __align__(16) __half  g_hs[2][(size_t)BB * HH];      // ping-pong fp16 h
__device__ unsigned              g_bar_cnt;                     // persistent-kernel barrier
__device__ float                 g_bias[GG];                     // reordered b_ih + b_hh

// ---------------------------------------------------------------------------
// PTX helpers (baseline ISA: cp.async / ldmatrix / mma.sync -- sm_80+)
// ---------------------------------------------------------------------------
__device__ __forceinline__ uint32_t smem_u32(const void* p) {
    uint32_t a;
    asm("{ .reg .u64 t; cvta.to.shared.u64 t, %1; cvt.u32.u64 %0, t; }" : "=r"(a) : "l"(p));
    return a;
}

#define CP_ASYNC16(sa, ga) \
    asm volatile("cp.async.cg.shared.global [%0], [%1], 16;" :: "r"(sa), "l"(ga))
#define CP_COMMIT() asm volatile("cp.async.commit_group;")
#define CP_WAIT1()  asm volatile("cp.async.wait_group 1;")

#define LDSM_X4(r0, r1, r2, r3, addr) \
    asm volatile("ldmatrix.sync.aligned.m8n8.x4.shared.b16 {%0,%1,%2,%3}, [%4];" \
                 : "=r"(r0), "=r"(r1), "=r"(r2), "=r"(r3) : "r"(addr))

#define MMA_F16(d, a, b) \
    asm volatile("mma.sync.aligned.m16n8k16.row.col.f32.f16.f16.f32 " \
                 "{%0,%1,%2,%3}, {%4,%5,%6,%7}, {%8,%9}, {%0,%1,%2,%3};" \
                 : "+f"((d)[0]), "+f"((d)[1]), "+f"((d)[2]), "+f"((d)[3]) \
                 : "r"((a)[0]), "r"((a)[1]), "r"((a)[2]), "r"((a)[3]), \
                   "r"((b)[0]), "r"((b)[1]))

// ---------------------------------------------------------------------------
// Shared GEMM body pieces (CTA tile 128x128, 8 warps = 4M x 2N, BK = 64)
// ---------------------------------------------------------------------------
struct Frag { float acc[2][8][4]; };

template<typename F>
__device__ __forceinline__ void compute_chunk(uint32_t sb, int lane, int wm, int wn,
                                              F& f) {
    const uint32_t aB = sb;
    const uint32_t bB = sb + TILE_BYTES;
#pragma unroll
    for (int k16 = 0; k16 < 4; k16++) {
        const int kb = k16 * 2 + (lane >> 4);
        uint32_t a1[2][4];
#pragma unroll
        for (int m = 0; m < 2; m++) {
            const int r = wm * 32 + m * 16 + (lane & 15);
            const uint32_t off = r * 128 + ((kb ^ (r & 7)) << 4);
            LDSM_X4(a1[m][0], a1[m][1], a1[m][2], a1[m][3], aB + off);
        }
        uint32_t bf[8][2];
#pragma unroll
        for (int np = 0; np < 4; np++) {
            const int r = wn * 64 + np * 16 + (lane & 15);
            const uint32_t off = r * 128 + ((kb ^ (r & 7)) << 4);
            uint32_t t0, t1, t2, t3;
            LDSM_X4(t0, t1, t2, t3, bB + off);
            bf[np*2][0] = t0; bf[np*2][1] = t2;
            bf[np*2+1][0] = t1; bf[np*2+1][1] = t3;
        }
#pragma unroll
        for (int m = 0; m < 2; m++)
#pragma unroll
            for (int n = 0; n < 8; n++)
                MMA_F16(f.acc[m][n], a1[m], bf[n]);
    }
}

// ---------------------------------------------------------------------------
// Persistent LSTM recurrence kernel: 128 CTAs, 128 timesteps, global barrier.
// CTA (tileM, tileN) owns batch rows [tileM*128,+128) x units [tileN*32,+32).
// c-state lives in registers (mapping is step-invariant per thread).
// ---------------------------------------------------------------------------
__global__ void __launch_bounds__(256, 1)
lstm_persistent_kernel(float* __restrict__ out)
{
    extern __shared__ char smem[];
    const int tid  = threadIdx.x;
    const int lane = tid & 31;
    const int wid  = tid >> 5;
    const int wm   = wid >> 1;
    const int wn   = wid & 1;
    const int tileN = blockIdx.x;      // 0..63
    const int tileM = blockIdx.y;      // 0..1
    const uint32_t sbase = smem_u32(smem);

    // Per-thread load slots: s=0..3 cover one 128x64 tile (16B per thread-slot)
    int goff[4];  uint32_t soff[4];
#pragma unroll
    for (int s = 0; s < 4; s++) {
        const int linear = tid + s * 256;      // 0..1023
        const int r  = linear >> 3;
        const int kb = linear & 7;
        goff[s] = r * HH + kb * 8;             // element offset (row stride HH)
        soff[s] = r * 128 + ((kb ^ (r & 7)) << 4);
    }

    const __half* bBase = g_whh + (size_t)(tileN * 128) * HH;

    float c_reg[2][8];
#pragma unroll
    for (int m = 0; m < 2; m++)
#pragma unroll
        for (int n = 0; n < 8; n++) c_reg[m][n] = 0.0f;

    const int odd = lane & 1;

    for (int t = 0; t < TT; t++) {
        const __half* aBase = g_hs[t & 1] + (size_t)(tileM * 128) * HH;

        Frag f;
#pragma unroll
        for (int m = 0; m < 2; m++)
#pragma unroll
            for (int n = 0; n < 8; n++)
#pragma unroll
                for (int v = 0; v < 4; v++) f.acc[m][n][v] = 0.0f;

        auto issue = [&](int it) {
            if (it < HH / 64) {
                const int k0 = it * 64;
                const uint32_t sb = sbase + (it % 3) * STAGE_BYTES;
#pragma unroll
                for (int s = 0; s < 4; s++)
                    CP_ASYNC16(sb + soff[s], aBase + goff[s] + k0);
#pragma unroll
                for (int s = 0; s < 4; s++)
                    CP_ASYNC16(sb + TILE_BYTES + soff[s], bBase + goff[s] + k0);
            }
            CP_COMMIT();
        };

        issue(0); issue(1);
        for (int it = 0; it < HH / 64; it++) {
            CP_WAIT1();
            __syncthreads();
            issue(it + 2);
            compute_chunk(sbase + (it % 3) * STAGE_BYTES, lane, wm, wn, f);
        }

        // ---- fused LSTM cell epilogue ----
        const int nxt = (t & 1) ^ 1;
        __half* hsN = g_hs[nxt];
#pragma unroll
        for (int m = 0; m < 2; m++) {
#pragma unroll
            for (int n = 0; n < 8; n++) {
                const float c0 = f.acc[m][n][0], c1 = f.acc[m][n][1];
                const float c2 = f.acc[m][n][2], c3 = f.acc[m][n][3];
                const float s0 = odd ? c0 : c2;
                const float s1 = odd ? c1 : c3;
                const float rx = __shfl_xor_sync(0xffffffffu, s0, 1);
                const float ry = __shfl_xor_sync(0xffffffffu, s1, 1);
                const float gi = odd ? rx : c0;
                const float gf = odd ? ry : c1;
                const float gg = odd ? c2 : rx;
                const float go = odd ? c3 : ry;
                const int b  = tileM * 128 + wm * 32 + m * 16 + (lane >> 2) + (odd ? 8 : 0);
                const int ug = tileN * 32 + wn * 16 + n * 2 + ((lane & 3) >> 1);

                const uint2 xw = *(const uint2*)(g_xg + ((size_t)b * TT + t) * GG + 4 * (size_t)ug);
                const float2 x01 = __half22float2(*(const __half2*)&xw.x);
                const float2 x23 = __half22float2(*(const __half2*)&xw.y);
                const float pi = gi + x01.x;
                const float pf = gf + x01.y;
                const float pg = gg + x23.x;
                const float po = go + x23.y;

                const float ig = 1.0f / (1.0f + __expf(-pi));
                const float fg = 1.0f / (1.0f + __expf(-pf));
                const float eg = __expf(-2.0f * fabsf(pg));
                const float tg = copysignf((1.0f - eg) / (1.0f + eg), pg);
                const float og = 1.0f / (1.0f + __expf(-po));

                const float cn = fg * c_reg[m][n] + ig * tg;
                c_reg[m][n] = cn;
                const float ec = __expf(-2.0f * fabsf(cn));
                const float th = copysignf((1.0f - ec) / (1.0f + ec), cn);
                const float h  = og * th;

                hsN[(size_t)b * HH + ug] = __float2half(h);
                if (t == TT - 1) out[(size_t)b * HH + ug] = h;
            }
        }

        // ---- global barrier (monotone counter; all 128 CTAs co-resident) ----
        __syncthreads();
        if (tid == 0) {
            __threadfence();
            atomicAdd(&g_bar_cnt, 1u);
            const unsigned target = (unsigned)(t + 1) * NBLK;
            while (*(volatile unsigned*)&g_bar_cnt < target) { }
            __threadfence();
        }
        __syncthreads();
    }
}

// ---------------------------------------------------------------------------
// Phase-1 kernel: xg = x @ W_ih^T + bias, fp16 output, 1-term fp16 inputs.
// ---------------------------------------------------------------------------
__global__ void __launch_bounds__(256, 1)
phase1_kernel()
{
    extern __shared__ char smem[];
    const int tid  = threadIdx.x;
    const int lane = tid & 31;
    const int wid  = tid >> 5;
    const int wm   = wid >> 1;
    const int wn   = wid & 1;
    const int tileN = blockIdx.x;
    const int tileM = blockIdx.y;
    const uint32_t sbase = smem_u32(smem);

    int goff[4];  uint32_t soff[4];
#pragma unroll
    for (int s = 0; s < 4; s++) {
        const int linear = tid + s * 256;
        const int r  = linear >> 3;
        const int kb = linear & 7;
        goff[s] = r * KSEG_X + kb * 8;
        soff[s] = r * 128 + ((kb ^ (r & 7)) << 4);
    }

    const __half* aBase = g_xs  + (size_t)(tileM * 128) * KSEG_X;
    const __half* bBase = g_wih + (size_t)(tileN * 128) * KSEG_X;

    Frag f;
#pragma unroll
    for (int m = 0; m < 2; m++)
#pragma unroll
        for (int n = 0; n < 8; n++)
#pragma unroll
            for (int v = 0; v < 4; v++) f.acc[m][n][v] = 0.0f;

    const int niter = KSEG_X / 64;   // 5
    auto issue = [&](int it) {
        if (it < niter) {
            const int k0 = it * 64;
            const uint32_t sb = sbase + (it % 3) * STAGE_BYTES;
#pragma unroll
            for (int s = 0; s < 4; s++)
                CP_ASYNC16(sb + soff[s], aBase + goff[s] + k0);
#pragma unroll
            for (int s = 0; s < 4; s++)
                CP_ASYNC16(sb + TILE_BYTES + soff[s], bBase + goff[s] + k0);
        }
        CP_COMMIT();
    };

    issue(0); issue(1);
    for (int it = 0; it < niter; it++) {
        CP_WAIT1();
        __syncthreads();
        issue(it + 2);
        compute_chunk(sbase + (it % 3) * STAGE_BYTES, lane, wm, wn, f);
    }

    // Epilogue: fp16 xg with bias
#pragma unroll
    for (int m = 0; m < 2; m++) {
        const int row0 = tileM * 128 + wm * 32 + m * 16 + (lane >> 2);
#pragma unroll
        for (int n = 0; n < 8; n++) {
            const int col = tileN * 128 + wn * 64 + n * 8 + 2 * (lane & 3);
            const float2 bz = *(const float2*)(g_bias + col);
            const __half2 v0 = __floats2half2_rn(f.acc[m][n][0] + bz.x,
                                                 f.acc[m][n][1] + bz.y);
            const __half2 v1 = __floats2half2_rn(f.acc[m][n][2] + bz.x,
                                                 f.acc[m][n][3] + bz.y);
            *(__half2*)(g_xg + (size_t)row0 * GG + col)       = v0;
            *(__half2*)(g_xg + (size_t)(row0 + 8) * GG + col) = v1;
        }
    }
}

// ---------------------------------------------------------------------------
// Prep kernels.  Reordered row r  <->  original row (r&3)*H + (r>>2).
// ---------------------------------------------------------------------------
__global__ void prep_whh_kernel(const float* __restrict__ W) {
    int idx = blockIdx.x * blockDim.x + threadIdx.x;
    if (idx >= GG * HH) return;
    int r = idx / HH, k = idx - r * HH;
    int orig = (r & 3) * HH + (r >> 2);
    g_whh[(size_t)r * HH + k] = __float2half(W[(size_t)orig * HH + k]);
}

__global__ void prep_wih_kernel(const float* __restrict__ W) {
    int idx = blockIdx.x * blockDim.x + threadIdx.x;
    if (idx >= GG * KSEG_X) return;
    int r = idx / KSEG_X, k = idx - r * KSEG_X;
    int orig = (r & 3) * HH + (r >> 2);
    float w = (k < EE) ? W[(size_t)orig * EE + k] : 0.0f;
    g_wih[(size_t)r * KSEG_X + k] = __float2half(w);
}

__global__ void prep_x_kernel(const float* __restrict__ x) {
    int idx = blockIdx.x * blockDim.x + threadIdx.x;
    if (idx >= BB * TT * KSEG_X) return;
    int m = idx / KSEG_X, k = idx - m * KSEG_X;
    g_xs[(size_t)m * KSEG_X + k] = __float2half((k < EE) ? x[(size_t)m * EE + k] : 0.0f);
}

__global__ void prep_bias_kernel(const float* __restrict__ b_ih,
                                 const float* __restrict__ b_hh) {
    int n = blockIdx.x * blockDim.x + threadIdx.x;
    if (n >= GG) return;
    int orig = (n & 3) * HH + (n >> 2);
    g_bias[n] = b_ih[orig] + b_hh[orig];
}

__global__ void init_state_kernel() {
    int i = blockIdx.x * blockDim.x + threadIdx.x;
    if (i == 0) g_bar_cnt = 0;
    if (i < BB * HH) g_hs[0][i] = __float2half(0.0f);
}

// ---------------------------------------------------------------------------
// Launch
// ---------------------------------------------------------------------------
extern "C" void kernel_launch(void* const* d_in, const int* in_sizes, int n_in,
                              void* d_out, int out_size) {
    const float* x    = (const float*)d_in[0];   // [B, T, E]
    const float* W_ih = (const float*)d_in[1];   // [4H, E]
    const float* W_hh = (const float*)d_in[2];   // [4H, H]
    const float* b_ih = (const float*)d_in[3];   // [4H]
    const float* b_hh = (const float*)d_in[4];   // [4H]
    float* out = (float*)d_out;                  // [B, H]

    cudaFuncSetAttribute(phase1_kernel,
                         cudaFuncAttributeMaxDynamicSharedMemorySize, SMEM_SZ);
    cudaFuncSetAttribute(lstm_persistent_kernel,
                         cudaFuncAttributeMaxDynamicSharedMemorySize, SMEM_SZ);

    // Prep
    prep_whh_kernel<<<(GG * HH + 255) / 256, 256>>>(W_hh);
    prep_wih_kernel<<<(GG * KSEG_X + 255) / 256, 256>>>(W_ih);
    prep_x_kernel<<<(BB * TT * KSEG_X + 255) / 256, 256>>>(x);
    prep_bias_kernel<<<(GG + 255) / 256, 256>>>(b_ih, b_hh);
    init_state_kernel<<<(BB * HH + 255) / 256, 256>>>();

    // Phase 1: xg (fp16) = x @ W_ih^T + bias
    {
        dim3 grid(GG / 128, (BB * TT) / 128);    // 64 x 256
        phase1_kernel<<<grid, 256, SMEM_SZ>>>();
    }

    // Phase 2: persistent fused LSTM recurrence (one launch, 128 steps)
    {
        dim3 grid(GG / 128, BB / 128);           // 64 x 2 = 128 CTAs
        lstm_persistent_kernel<<<grid, 256, SMEM_SZ>>>(out);
    }
}

// round 13
// speedup vs baseline: 9.8446x; 1.0167x over previous
#include <cuda_runtime.h>
#include <cuda_fp16.h>
#include <stdint.h>
#include <math.h>

// ---------------------------------------------------------------------------
// Problem constants
// ---------------------------------------------------------------------------
#define BB 256
#define TT 128
#define EE 300
#define HH 2048
#define GG 8192      // 4*H

#define KSEG_X 320   // phase-1 K (300 padded to 320)

#define TILE_BYTES 16384            // 128 rows x 128 bytes (64 fp16), swizzled image
#define STAGE_BYTES (2 * TILE_BYTES)
#define SMEM_SZ (3 * STAGE_BYTES)   // 98304

#define NBLK 128                    // persistent grid size (64 x 2)
#define NCHUNK 32                   // K chunks per step (2048/64)

// ---------------------------------------------------------------------------
// Device scratch (no allocations allowed)
// ---------------------------------------------------------------------------
__device__ __align__(16) __half  g_xg[(size_t)BB * TT * GG];    // fp16 gate-interleaved xg
// W_hh pre-tiled + pre-swizzled: [64 tileN][32 chunk][16384 B smem image]
__device__ __align__(16) unsigned char g_whh_t[(size_t)64 * NCHUNK * TILE_BYTES];
// h state pre-tiled + pre-swizzled, ping-pong: [2][2 tileM][32 chunk][16384 B]
__device__ __align__(16) unsigned char g_ht[2][(size_t)2 * NCHUNK * TILE_BYTES];
__device__ __align__(16) __half  g_wih[(size_t)GG * KSEG_X];    // plain fp16, rows reordered
__device__ __align__(16) __half  g_xs[(size_t)BB * TT * KSEG_X];// plain fp16 x, K padded
__device__ unsigned              g_bar_cnt;                     // persistent-kernel barrier
__device__ float                 g_bias[GG];                     // reordered b_ih + b_hh

// ---------------------------------------------------------------------------
// PTX helpers (baseline ISA: cp.async(.bulk) / mbarrier / ldmatrix / mma.sync)
// ---------------------------------------------------------------------------
__device__ __forceinline__ uint32_t smem_u32(const void* p) {
    uint32_t a;
    asm("{ .reg .u64 t; cvta.to.shared.u64 t, %1; cvt.u32.u64 %0, t; }" : "=r"(a) : "l"(p));
    return a;
}

#define CP_ASYNC16(sa, ga) \
    asm volatile("cp.async.cg.shared.global [%0], [%1], 16;" :: "r"(sa), "l"(ga))
#define CP_COMMIT() asm volatile("cp.async.commit_group;")
#define CP_WAIT1()  asm volatile("cp.async.wait_group 1;")

#define MBAR_INIT(a, c) \
    asm volatile("mbarrier.init.shared.b64 [%0], %1;" :: "r"(a), "r"((uint32_t)(c)) : "memory")
#define MBAR_EXPECT_TX(a, bytes) \
    asm volatile("mbarrier.arrive.expect_tx.shared.b64 _, [%0], %1;" \
                 :: "r"(a), "r"((uint32_t)(bytes)) : "memory")
#define BULK_G2S(dst, src, bytes, mbar) \
    asm volatile("cp.async.bulk.shared::cluster.global.mbarrier::complete_tx::bytes " \
                 "[%0], [%1], %2, [%3];" \
                 :: "r"(dst), "l"(src), "r"((uint32_t)(bytes)), "r"(mbar) : "memory")

#define MBAR_WAIT(a, ph) do {                                                         \
    uint32_t _m = (a), _p = (uint32_t)(ph), _d;                                       \
    asm volatile("{ .reg .pred p; "                                                   \
        "mbarrier.try_wait.parity.acquire.cta.shared::cta.b64 p, [%1], %2; "          \
        "selp.b32 %0,1,0,p; }"                                                        \
        : "=r"(_d) : "r"(_m), "r"(_p) : "memory");                                    \
    if (!_d) {                                                                        \
        asm volatile("{ .reg .pred P1; "                                              \
            "WL_%=: mbarrier.try_wait.parity.acquire.cta.shared::cta.b64 P1, [%0], %1, 0x989680; " \
            "@P1 bra.uni WD_%=; bra.uni WL_%=; WD_%=: }"                              \
            :: "r"(_m), "r"(_p) : "memory");                                          \
    }                                                                                 \
} while (0)

#define LDSM_X4(r0, r1, r2, r3, addr) \
    asm volatile("ldmatrix.sync.aligned.m8n8.x4.shared.b16 {%0,%1,%2,%3}, [%4];" \
                 : "=r"(r0), "=r"(r1), "=r"(r2), "=r"(r3) : "r"(addr))

#define MMA_F16(d, a, b) \
    asm volatile("mma.sync.aligned.m16n8k16.row.col.f32.f16.f16.f32 " \
                 "{%0,%1,%2,%3}, {%4,%5,%6,%7}, {%8,%9}, {%0,%1,%2,%3};" \
                 : "+f"((d)[0]), "+f"((d)[1]), "+f"((d)[2]), "+f"((d)[3]) \
                 : "r"((a)[0]), "r"((a)[1]), "r"((a)[2]), "r"((a)[3]), \
                   "r"((b)[0]), "r"((b)[1]))

// Swizzled byte offset of element (row r 0..127, col kc 0..63) inside a tile image
__device__ __forceinline__ uint32_t tile_off(int r, int kc) {
    return (uint32_t)(r * 128 + ((((kc >> 3) ^ (r & 7))) << 4) + (kc & 7) * 2);
}

// ---------------------------------------------------------------------------
// GEMM compute (CTA tile 128x128, 8 warps = 4M x 2N, BK = 64)
// ---------------------------------------------------------------------------
struct Frag { float acc[2][8][4]; };

__device__ __forceinline__ void compute_chunk(uint32_t sb, int lane, int wm, int wn,
                                              Frag& f) {
    const uint32_t aB = sb;
    const uint32_t bB = sb + TILE_BYTES;
#pragma unroll
    for (int k16 = 0; k16 < 4; k16++) {
        const int kb = k16 * 2 + (lane >> 4);
        uint32_t a1[2][4];
#pragma unroll
        for (int m = 0; m < 2; m++) {
            const int r = wm * 32 + m * 16 + (lane & 15);
            const uint32_t off = r * 128 + ((kb ^ (r & 7)) << 4);
            LDSM_X4(a1[m][0], a1[m][1], a1[m][2], a1[m][3], aB + off);
        }
        uint32_t bf[8][2];
#pragma unroll
        for (int np = 0; np < 4; np++) {
            const int r = wn * 64 + np * 16 + (lane & 15);
            const uint32_t off = r * 128 + ((kb ^ (r & 7)) << 4);
            uint32_t t0, t1, t2, t3;
            LDSM_X4(t0, t1, t2, t3, bB + off);
            bf[np*2][0] = t0; bf[np*2][1] = t2;
            bf[np*2+1][0] = t1; bf[np*2+1][1] = t3;
        }
#pragma unroll
        for (int m = 0; m < 2; m++)
#pragma unroll
            for (int n = 0; n < 8; n++)
                MMA_F16(f.acc[m][n], a1[m], bf[n]);
    }
}

// ---------------------------------------------------------------------------
// Persistent LSTM recurrence kernel: 128 CTAs, 128 timesteps, global barrier.
// Tiles arrive via cp.async.bulk (UBLKCP) from pre-swizzled global images.
// ---------------------------------------------------------------------------
__global__ void __launch_bounds__(256, 1)
lstm_persistent_kernel(float* __restrict__ out)
{
    extern __shared__ char smem[];
    __shared__ __align__(8) unsigned long long mbar[3];

    const int tid  = threadIdx.x;
    const int lane = tid & 31;
    const int wid  = tid >> 5;
    const int wm   = wid >> 1;
    const int wn   = wid & 1;
    const int tileN = blockIdx.x;      // 0..63
    const int tileM = blockIdx.y;      // 0..1
    const uint32_t sbase = smem_u32(smem);
    uint32_t mb[3];
#pragma unroll
    for (int s = 0; s < 3; s++) mb[s] = smem_u32(&mbar[s]);

    if (tid == 0) {
        MBAR_INIT(mb[0], 1); MBAR_INIT(mb[1], 1); MBAR_INIT(mb[2], 1);
    }
    __syncthreads();

    const unsigned char* bTiles = g_whh_t + (size_t)tileN * NCHUNK * TILE_BYTES;

    int ph[3] = {0, 0, 0};             // per-stage phase counters (all threads)

    float c_reg[2][8];
#pragma unroll
    for (int m = 0; m < 2; m++)
#pragma unroll
        for (int n = 0; n < 8; n++) c_reg[m][n] = 0.0f;

    const int odd = lane & 1;

    for (int t = 0; t < TT; t++) {
        const unsigned char* aTiles = g_ht[t & 1] + (size_t)tileM * NCHUNK * TILE_BYTES;

        Frag f;
#pragma unroll
        for (int m = 0; m < 2; m++)
#pragma unroll
            for (int n = 0; n < 8; n++)
#pragma unroll
                for (int v = 0; v < 4; v++) f.acc[m][n][v] = 0.0f;

        auto issue = [&](int it) {
            if (tid == 0 && it < NCHUNK) {
                const int s = it % 3;
                const uint32_t sb = sbase + s * STAGE_BYTES;
                MBAR_EXPECT_TX(mb[s], STAGE_BYTES);
                BULK_G2S(sb,              aTiles + (size_t)it * TILE_BYTES, TILE_BYTES, mb[s]);
                BULK_G2S(sb + TILE_BYTES, bTiles + (size_t)it * TILE_BYTES, TILE_BYTES, mb[s]);
            }
        };

        issue(0); issue(1);
        for (int it = 0; it < NCHUNK; it++) {
            const int s = it % 3;
            MBAR_WAIT(mb[s], ph[s] & 1);
            ph[s]++;
            __syncthreads();           // all warps done with buffer (it-1)%3
            issue(it + 2);
            compute_chunk(sbase + s * STAGE_BYTES, lane, wm, wn, f);
        }

        // ---- fused LSTM cell epilogue ----
        const int nxt = (t & 1) ^ 1;
        unsigned char* hOut = g_ht[nxt];
#pragma unroll
        for (int m = 0; m < 2; m++) {
#pragma unroll
            for (int n = 0; n < 8; n++) {
                const float c0 = f.acc[m][n][0], c1 = f.acc[m][n][1];
                const float c2 = f.acc[m][n][2], c3 = f.acc[m][n][3];
                const float s0 = odd ? c0 : c2;
                const float s1 = odd ? c1 : c3;
                const float rx = __shfl_xor_sync(0xffffffffu, s0, 1);
                const float ry = __shfl_xor_sync(0xffffffffu, s1, 1);
                const float gi = odd ? rx : c0;
                const float gf = odd ? ry : c1;
                const float gg = odd ? c2 : rx;
                const float go = odd ? c3 : ry;
                const int b  = tileM * 128 + wm * 32 + m * 16 + (lane >> 2) + (odd ? 8 : 0);
                const int ug = tileN * 32 + wn * 16 + n * 2 + ((lane & 3) >> 1);

                const uint2 xw = *(const uint2*)(g_xg + ((size_t)b * TT + t) * GG + 4 * (size_t)ug);
                const float2 x01 = __half22float2(*(const __half2*)&xw.x);
                const float2 x23 = __half22float2(*(const __half2*)&xw.y);
                const float pi = gi + x01.x;
                const float pf = gf + x01.y;
                const float pg = gg + x23.x;
                const float po = go + x23.y;

                const float ig = 1.0f / (1.0f + __expf(-pi));
                const float fg = 1.0f / (1.0f + __expf(-pf));
                const float eg = __expf(-2.0f * fabsf(pg));
                const float tg = copysignf((1.0f - eg) / (1.0f + eg), pg);
                const float og = 1.0f / (1.0f + __expf(-po));

                const float cn = fg * c_reg[m][n] + ig * tg;
                c_reg[m][n] = cn;
                const float ec = __expf(-2.0f * fabsf(cn));
                const float th = copysignf((1.0f - ec) / (1.0f + ec), cn);
                const float h  = og * th;

                // tiled + swizzled h store for next step's bulk-DMA A tiles
                const size_t hoff = ((size_t)(b >> 7) * NCHUNK + (ug >> 6)) * TILE_BYTES
                                  + tile_off(b & 127, ug & 63);
                *(__half*)(hOut + hoff) = __float2half(h);
                if (t == TT - 1) out[(size_t)b * HH + ug] = h;
            }
        }

        // ---- global barrier (monotone counter; all 128 CTAs co-resident) ----
        __syncthreads();
        if (tid == 0) {
            __threadfence();
            atomicAdd(&g_bar_cnt, 1u);
            const unsigned target = (unsigned)(t + 1) * NBLK;
            while (*(volatile unsigned*)&g_bar_cnt < target) { }
            __threadfence();
        }
        __syncthreads();
    }
}

// ---------------------------------------------------------------------------
// Phase-1 kernel: xg = x @ W_ih^T + bias, fp16 output (LDGSTS pipeline).
// ---------------------------------------------------------------------------
__global__ void __launch_bounds__(256, 1)
phase1_kernel()
{
    extern __shared__ char smem[];
    const int tid  = threadIdx.x;
    const int lane = tid & 31;
    const int wid  = tid >> 5;
    const int wm   = wid >> 1;
    const int wn   = wid & 1;
    const int tileN = blockIdx.x;
    const int tileM = blockIdx.y;
    const uint32_t sbase = smem_u32(smem);

    int goff[4];  uint32_t soff[4];
#pragma unroll
    for (int s = 0; s < 4; s++) {
        const int linear = tid + s * 256;
        const int r  = linear >> 3;
        const int kb = linear & 7;
        goff[s] = r * KSEG_X + kb * 8;
        soff[s] = r * 128 + ((kb ^ (r & 7)) << 4);
    }

    const __half* aBase = g_xs  + (size_t)(tileM * 128) * KSEG_X;
    const __half* bBase = g_wih + (size_t)(tileN * 128) * KSEG_X;

    Frag f;
#pragma unroll
    for (int m = 0; m < 2; m++)
#pragma unroll
        for (int n = 0; n < 8; n++)
#pragma unroll
            for (int v = 0; v < 4; v++) f.acc[m][n][v] = 0.0f;

    const int niter = KSEG_X / 64;   // 5
    auto issue = [&](int it) {
        if (it < niter) {
            const int k0 = it * 64;
            const uint32_t sb = sbase + (it % 3) * STAGE_BYTES;
#pragma unroll
            for (int s = 0; s < 4; s++)
                CP_ASYNC16(sb + soff[s], aBase + goff[s] + k0);
#pragma unroll
            for (int s = 0; s < 4; s++)
                CP_ASYNC16(sb + TILE_BYTES + soff[s], bBase + goff[s] + k0);
        }
        CP_COMMIT();
    };

    issue(0); issue(1);
    for (int it = 0; it < niter; it++) {
        CP_WAIT1();
        __syncthreads();
        issue(it + 2);
        compute_chunk(sbase + (it % 3) * STAGE_BYTES, lane, wm, wn, f);
    }

#pragma unroll
    for (int m = 0; m < 2; m++) {
        const int row0 = tileM * 128 + wm * 32 + m * 16 + (lane >> 2);
#pragma unroll
        for (int n = 0; n < 8; n++) {
            const int col = tileN * 128 + wn * 64 + n * 8 + 2 * (lane & 3);
            const float2 bz = *(const float2*)(g_bias + col);
            const __half2 v0 = __floats2half2_rn(f.acc[m][n][0] + bz.x,
                                                 f.acc[m][n][1] + bz.y);
            const __half2 v1 = __floats2half2_rn(f.acc[m][n][2] + bz.x,
                                                 f.acc[m][n][3] + bz.y);
            *(__half2*)(g_xg + (size_t)row0 * GG + col)       = v0;
            *(__half2*)(g_xg + (size_t)(row0 + 8) * GG + col) = v1;
        }
    }
}

// ---------------------------------------------------------------------------
// Prep kernels.  Reordered row r  <->  original row (r&3)*H + (r>>2).
// ---------------------------------------------------------------------------
__global__ void prep_whh_kernel(const float* __restrict__ W) {
    int idx = blockIdx.x * blockDim.x + threadIdx.x;
    if (idx >= GG * HH) return;
    int rg = idx / HH, k = idx - rg * HH;       // reordered row, K col
    int orig = (rg & 3) * HH + (rg >> 2);
    const float w = W[(size_t)orig * HH + k];
    const size_t off = ((size_t)(rg >> 7) * NCHUNK + (k >> 6)) * TILE_BYTES
                     + tile_off(rg & 127, k & 63);
    *(__half*)(g_whh_t + off) = __float2half(w);
}

__global__ void prep_wih_kernel(const float* __restrict__ W) {
    int idx = blockIdx.x * blockDim.x + threadIdx.x;
    if (idx >= GG * KSEG_X) return;
    int r = idx / KSEG_X, k = idx - r * KSEG_X;
    int orig = (r & 3) * HH + (r >> 2);
    float w = (k < EE) ? W[(size_t)orig * EE + k] : 0.0f;
    g_wih[(size_t)r * KSEG_X + k] = __float2half(w);
}

__global__ void prep_x_kernel(const float* __restrict__ x) {
    int idx = blockIdx.x * blockDim.x + threadIdx.x;
    if (idx >= BB * TT * KSEG_X) return;
    int m = idx / KSEG_X, k = idx - m * KSEG_X;
    g_xs[(size_t)m * KSEG_X + k] = __float2half((k < EE) ? x[(size_t)m * EE + k] : 0.0f);
}

__global__ void prep_bias_kernel(const float* __restrict__ b_ih,
                                 const float* __restrict__ b_hh) {
    int n = blockIdx.x * blockDim.x + threadIdx.x;
    if (n >= GG) return;
    int orig = (n & 3) * HH + (n >> 2);
    g_bias[n] = b_ih[orig] + b_hh[orig];
}

__global__ void init_state_kernel() {
    int i = blockIdx.x * blockDim.x + threadIdx.x;
    if (i == 0) g_bar_cnt = 0;
    const int nwords = 2 * NCHUNK * TILE_BYTES / 4;   // zero ping buffer 0 (h=0)
    if (i < nwords) ((uint32_t*)g_ht[0])[i] = 0u;
}

// ---------------------------------------------------------------------------
// Launch
// ---------------------------------------------------------------------------
extern "C" void kernel_launch(void* const* d_in, const int* in_sizes, int n_in,
                              void* d_out, int out_size) {
    const float* x    = (const float*)d_in[0];   // [B, T, E]
    const float* W_ih = (const float*)d_in[1];   // [4H, E]
    const float* W_hh = (const float*)d_in[2];   // [4H, H]
    const float* b_ih = (const float*)d_in[3];   // [4H]
    const float* b_hh = (const float*)d_in[4];   // [4H]
    float* out = (float*)d_out;                  // [B, H]

    cudaFuncSetAttribute(phase1_kernel,
                         cudaFuncAttributeMaxDynamicSharedMemorySize, SMEM_SZ);
    cudaFuncSetAttribute(lstm_persistent_kernel,
                         cudaFuncAttributeMaxDynamicSharedMemorySize, SMEM_SZ);

    // Prep
    prep_whh_kernel<<<(GG * HH + 255) / 256, 256>>>(W_hh);
    prep_wih_kernel<<<(GG * KSEG_X + 255) / 256, 256>>>(W_ih);
    prep_x_kernel<<<(BB * TT * KSEG_X + 255) / 256, 256>>>(x);
    prep_bias_kernel<<<(GG + 255) / 256, 256>>>(b_ih, b_hh);
    init_state_kernel<<<(2 * NCHUNK * TILE_BYTES / 4 + 255) / 256, 256>>>();

    // Phase 1: xg (fp16) = x @ W_ih^T + bias
    {
        dim3 grid(GG / 128, (BB * TT) / 128);    // 64 x 256
        phase1_kernel<<<grid, 256, SMEM_SZ>>>();
    }

    // Phase 2: persistent fused LSTM recurrence (one launch, 128 steps)
    {
        dim3 grid(GG / 128, BB / 128);           // 64 x 2 = 128 CTAs
        lstm_persistent_kernel<<<grid, 256, SMEM_SZ>>>(out);
    }
}